// round 9
// baseline (speedup 1.0000x reference)
#include <cuda_runtime.h>
#include <cuda_fp16.h>

// ForwardWarp: forward splatting with Gaussian softmax weights.
// img, counts: (8,1,720,1280) f32; flo: (8,2,720,1280) f32 (ch0 = y shifts W, ch1 = x shifts H)
// out: [0:S) = img_warp / (one_warp + eps), [S:2S) = one_warp
//
// Splat: one branchless red.global.add.noftz.v4.f16x2 per pixel into 4 parity copies
// (pr=ix1&1, pc=iy1&1), rowpair-interleaved layout (see R8). At the LTS RED quantum
// floor (2 x 8B quanta/pixel ~ 12.9us/chunk). Normalize: 8-row x 2-col tiles so the
// pr=1 copies are read ~1.25x instead of 2x; all-vector loads, streaming cache hints.
// Scratch reused across 4 batch chunks (29.6MB, L2-resident); memsetAsync re-zeroes.

static constexpr int N_ = 8;
static constexpr int H_ = 720;
static constexpr int W_ = 1280;
static constexpr int S_ = N_ * H_ * W_;     // 7,372,800
static constexpr float EPS_ = 1e-6f;

static constexpr int CHUNKS_ = 4;           // 2 images per chunk
static constexpr int PC_ = S_ / CHUNKS_;    // 1,843,200 pixels per chunk

static constexpr int NP_ = 361;             // pair-rows per copy (incl. pads)
static constexpr int WPAD_ = 2564;          // words per pair-row (16B multiple)
static constexpr int COPY_WORDS_ = NP_ * WPAD_;            // per copy per image
static constexpr int SCR_WORDS_ = 4 * 2 * COPY_WORDS_;     // 29.6MB

__device__ __align__(16) unsigned int g_S[SCR_WORDS_];     // BSS zero; memset restores per chunk

__device__ __forceinline__ void red_v4h2(unsigned int* p, unsigned int s0, unsigned int s1,
                                         unsigned int s2, unsigned int s3) {
    asm volatile("red.global.add.noftz.v4.f16x2 [%0], {%1, %2, %3, %4};"
                 :: "l"(p), "r"(s0), "r"(s1), "r"(s2), "r"(s3) : "memory");
}
__device__ __forceinline__ unsigned int pack_h2(float a, float b) {
    __half2 h = __float22half2_rn(make_float2(a, b));
    return *reinterpret_cast<unsigned int*>(&h);
}
__device__ __forceinline__ float2 unpack_h2(unsigned int u) {
    return __half22float2(*reinterpret_cast<__half2*>(&u));
}

__global__ void __launch_bounds__(256) splat_kernel(
    const float* __restrict__ img,
    const float* __restrict__ counts,
    const float* __restrict__ flo,
    int chunk)
{
    int idx = chunk * PC_ + blockIdx.x * blockDim.x + threadIdx.x;

    int w  = idx % W_;
    int hw = idx / W_;
    int h  = hw % H_;
    int n  = hw / H_;
    int ni = n & 1;                 // image within chunk

    int flo_base = ((n * 2) * H_ + h) * W_ + w;
    float y = __ldcs(flo + flo_base);
    float x = __ldcs(flo + flo_base + H_ * W_);

    float im = __ldcs(img + idx);
    float c  = __ldcs(counts + idx);

    float x1 = floorf(x);
    float y1 = floorf(y);
    float fx = x - x1;
    float fy = y - y1;
    float gx = fx - 1.0f;
    float gy = fy - 1.0f;

    float dx1 = fx * fx, dx2 = gx * gx;
    float dy1 = fy * fy, dy2 = gy * gy;

    float w11 = __expf(-(dx1 + dy1));   // row ix1, col iy1
    float w12 = __expf(-(dx1 + dy2));   // row ix1, col iy2
    float w21 = __expf(-(dx2 + dy1));   // row ix2, col iy1
    float w22 = __expf(-(dx2 + dy2));   // row ix2, col iy2
    float inv = 1.0f / (w11 + w12 + w21 + w22);
    float cinv = c * inv;

    int ix1 = (int)x1 + h;
    int iy1 = (int)y1 + w;

    if (ix1 < -1 || ix1 > H_ - 1 || iy1 < -1 || iy1 > W_ - 1) return;

    int pr = ix1 & 1;                     // (-1 & 1) == 1
    int pc = iy1 & 1;
    int P  = (ix1 + pr) >> 1;
    int wv = 2 * iy1 + 2 * pc;

    unsigned int* p = g_S + ((((pr * 2 + pc) * 2 + ni) * NP_ + P) * WPAD_ + wv);

    // word order in footprint: [ (r1,c1), (r2,c1), (r1,c2), (r2,c2) ]
    red_v4h2(p,
             pack_h2(im * (w11 * cinv), w11 * cinv),
             pack_h2(im * (w21 * cinv), w21 * cinv),
             pack_h2(im * (w12 * cinv), w12 * cinv),
             pack_h2(im * (w22 * cinv), w22 * cinv));
}

// One thread per 8-row x 2-col output tile: rows 8r..8r+7, cols {2Y, 2Y+1}, image ni.
// pr=0 copies: pairs 4r..4r+3 exactly; pr=1 copies: pairs 4r..4r+4 (edge pairs half-used).
__global__ void __launch_bounds__(256) normalize_kernel(float* __restrict__ out, int chunk)
{
    int t = blockIdx.x * blockDim.x + threadIdx.x;   // 0 .. 115199 per chunk
    int Y  = t % (W_ / 2);          // 0..639
    int rm = t / (W_ / 2);
    int r  = rm % (H_ / 8);         // 0..89
    int ni = rm / (H_ / 8);         // 0..1
    int n  = chunk * 2 + ni;

    const unsigned int* c00 = g_S + ((0 * 2 + ni) * NP_) * WPAD_;
    const unsigned int* c01 = g_S + ((1 * 2 + ni) * NP_) * WPAD_;
    const unsigned int* c10 = g_S + ((2 * 2 + ni) * NP_) * WPAD_;
    const unsigned int* c11 = g_S + ((3 * 2 + ni) * NP_) * WPAD_;

    int q = 4 * Y;
    int pbase = 4 * r;              // first pair-row of this tile

    // ---- loads (all vector, streaming) ----
    uint4 v[4];                     // c00 pair 4r+j: {(2p,2Y),(2p+1,2Y),(2p,2Y+1),(2p+1,2Y+1)}
    uint2 u0[4], u1[4];             // c01 pair 4r+j: col 2Y rows {2p,2p+1}; col 2Y+1
    uint4 A[5];                     // c10 pair 4r+k: rows {2P-1,2P} x cols {2Y,2Y+1}
    uint2 E[5], G[5];               // c11 pair 4r+k: col 2Y rows {2P-1,2P}; col 2Y+1

    #pragma unroll
    for (int j = 0; j < 4; j++) {
        int row = (pbase + j) * WPAD_;
        v[j]  = __ldcs(reinterpret_cast<const uint4*>(c00 + row + q));
        u0[j] = __ldcs(reinterpret_cast<const uint2*>(c01 + row + q + 2));
        u1[j] = __ldcs(reinterpret_cast<const uint2*>(c01 + row + q + 4));
    }
    #pragma unroll
    for (int k = 0; k < 5; k++) {
        int row = (pbase + k) * WPAD_;
        A[k] = __ldcs(reinterpret_cast<const uint4*>(c10 + row + q));
        E[k] = __ldcs(reinterpret_cast<const uint2*>(c11 + row + q + 2));
        G[k] = __ldcs(reinterpret_cast<const uint2*>(c11 + row + q + 4));
    }

    // ---- accumulate + write per output row ----
    int obase = ((n * H_) + 8 * r) * W_ + 2 * Y;

    #pragma unroll
    for (int i = 0; i < 8; i++) {
        int j  = i >> 1;            // pr=0 pair index
        int dr = i & 1;

        // c00 / c01 (pr=0): pair j
        unsigned int w00c0 = dr ? v[j].y : v[j].x;
        unsigned int w00c1 = dr ? v[j].w : v[j].z;
        unsigned int w01c0 = dr ? u0[j].y : u0[j].x;
        unsigned int w01c1 = dr ? u1[j].y : u1[j].x;

        // c10 / c11 (pr=1): even i -> pair i/2 odd word; odd i -> pair (i+1)/2 even word
        int k = (i + 1) >> 1;
        unsigned int w10c0 = (i & 1) ? A[k].x : A[k].y;
        unsigned int w10c1 = (i & 1) ? A[k].z : A[k].w;
        unsigned int w11c0 = (i & 1) ? E[k].x : E[k].y;
        unsigned int w11c1 = (i & 1) ? G[k].x : G[k].y;

        float2 f0 = unpack_h2(w00c0), f1 = unpack_h2(w01c0), f2 = unpack_h2(w10c0), f3 = unpack_h2(w11c0);
        float2 g0 = unpack_h2(w00c1), g1 = unpack_h2(w01c1), g2 = unpack_h2(w10c1), g3 = unpack_h2(w11c1);

        float num0 = (f0.x + f1.x) + (f2.x + f3.x);
        float den0 = (f0.y + f1.y) + (f2.y + f3.y);
        float num1 = (g0.x + g1.x) + (g2.x + g3.x);
        float den1 = (g0.y + g1.y) + (g2.y + g3.y);

        int o = obase + i * W_;
        __stcs(reinterpret_cast<float2*>(out + o),
               make_float2(num0 / (den0 + EPS_), num1 / (den1 + EPS_)));
        __stcs(reinterpret_cast<float2*>(out + S_ + o),
               make_float2(den0, den1));
    }
}

extern "C" void kernel_launch(void* const* d_in, const int* in_sizes, int n_in,
                              void* d_out, int out_size)
{
    const float* img    = (const float*)d_in[0];
    const float* counts = (const float*)d_in[1];
    const float* flo    = (const float*)d_in[2];
    float* out = (float*)d_out;

    void* scr = nullptr;
    cudaGetSymbolAddress(&scr, g_S);

    int splat_blocks = PC_ / 256;                         // 7200
    int norm_blocks  = (PC_ / 16) / 256;                  // 450 (16 cells per thread)

    for (int chunk = 0; chunk < CHUNKS_; chunk++) {
        splat_kernel<<<splat_blocks, 256>>>(img, counts, flo, chunk);
        normalize_kernel<<<norm_blocks, 256>>>(out, chunk);
        cudaMemsetAsync(scr, 0, (size_t)SCR_WORDS_ * sizeof(unsigned int));
    }
}